// round 9
// baseline (speedup 1.0000x reference)
#include <cuda_runtime.h>
#include <cuda_bf16.h>

#define B 64
#define L 1024
#define D 1024
#define S 32

#define LP 4            // token-chunk partitions
#define LCH (L / LP)    // 256 tokens per CTA
#define TPB 256         // thread owns one float4 -> full D row per CTA
#define U 8             // tokens per front-batched burst (8 x LDG.128 in flight)

#define TPC 128         // k_cos threads
#define QB  4           // bs handled per k_cos block
#define NCOS (B * S / QB)   // 512 blocks

// Scratch. Layout: g_part[((b*S+s)*LP + lp) * D] -> per-(b,s) partials contiguous.
__device__ float g_part[B * S * LP * D];   // 32 MB
__device__ float g_cntp[B * LP * S];
__device__ float g_cos[B * S];
__device__ int   g_ctr = 0;                // last-block election; self-resets

// ---------------------------------------------------------------------------
// Kernel 1: partial segment sums. One CTA per (batch, token-chunk); streams a
// fully CONTIGUOUS 1 MB region (256 tokens x 4 KB). 128 KB smem accumulator,
// each thread owns one float4 column -> conflict-free, race-free scatter-add.
// ---------------------------------------------------------------------------
__global__ __launch_bounds__(TPB) void k_accum(const int* __restrict__ attr,
                                               const float* __restrict__ text) {
    extern __shared__ float4 acc[];        // S * TPB float4 = 128 KB
    __shared__ signed char slab[LCH];
    __shared__ int scnt[S];

    const int b   = blockIdx.x;
    const int lp  = blockIdx.y;
    const int tid = threadIdx.x;

    #pragma unroll
    for (int i = tid; i < S * TPB; i += TPB) acc[i] = make_float4(0.f,0.f,0.f,0.f);
    if (tid < S) scnt[tid] = 0;

    const int* ab = attr + b * L + lp * LCH;
    for (int i = tid; i < LCH; i += TPB) slab[i] = (signed char)(ab[i] - 1);
    __syncthreads();

    const float4* tb = (const float4*)(text + (size_t)b * L * D
                                            + (size_t)lp * LCH * D) + tid;

    #pragma unroll 1
    for (int l = 0; l < LCH; l += U) {
        float4 v[U];
        #pragma unroll
        for (int u = 0; u < U; u++)
            v[u] = __ldcs(tb + (size_t)(l + u) * (D / 4));   // 8 LDG.128 in flight
        int lw[U / 4];
        #pragma unroll
        for (int j = 0; j < U / 4; j++)
            lw[j] = ((const int*)slab)[(l >> 2) + j];
        #pragma unroll
        for (int u = 0; u < U; u++) {                        // consume in load order
            int s = (lw[u >> 2] << (24 - 8 * (u & 3))) >> 24; // sign-extend byte
            if (s >= 0) {
                float4 a = acc[s * TPB + tid];
                a.x += v[u].x; a.y += v[u].y; a.z += v[u].z; a.w += v[u].w;
                acc[s * TPB + tid] = a;
            }
        }
    }

    // per-chunk counts (this CTA is unique for (b,lp); shared atomics, determ.)
    for (int i = tid; i < LCH; i += TPB) {
        int s = slab[i];
        if (s >= 0) atomicAdd(&scnt[s], 1);
    }
    __syncthreads();

    // write-out: per s, a contiguous 4 KB slice (each element written once)
    float4* op = (float4*)g_part + ((size_t)b * S * LP + lp) * (D / 4) + tid;
    #pragma unroll
    for (int s = 0; s < S; s++)
        op[(size_t)s * LP * (D / 4)] = acc[s * TPB + tid];
    if (tid < S) g_cntp[(b * LP + lp) * S + tid] = (float)scnt[tid];
}

// ---------------------------------------------------------------------------
// Kernel 2: cosine per (b,s), QB=4 per block (longer-lived blocks), folds the
// LP partials (now contiguous 16 KB per bs) + fused deterministic final.
// ---------------------------------------------------------------------------
__global__ __launch_bounds__(TPC) void k_cos(const float* __restrict__ Vgs,
                                             float* __restrict__ out) {
    const int tid  = threadIdx.x;
    const int w    = tid >> 5, lane = tid & 31;
    __shared__ float r0[4], r1[4], r2[4];

    #pragma unroll 1
    for (int q = 0; q < QB; q++) {
        const int bs = blockIdx.x * QB + q;
        const int b  = bs / S, sloc = bs - (bs / S) * S;

        const float4* vg = (const float4*)(Vgs + (size_t)bs * D);
        const float4* pp = (const float4*)g_part + (size_t)bs * LP * (D / 4);

        float cnt = 0.0f;
        #pragma unroll
        for (int lp = 0; lp < LP; lp++) cnt += g_cntp[(b * LP + lp) * S + sloc];
        const float inv = (cnt > 0.0f) ? (1.0f / cnt) : 0.0f;

        float dvm = 0.0f, dmm = 0.0f, dvv = 0.0f;
        #pragma unroll 2
        for (int d = tid; d < D / 4; d += TPC) {
            float4 a0 = pp[d];
            float4 a1 = pp[d + 1 * (D / 4)];
            float4 a2 = pp[d + 2 * (D / 4)];
            float4 a3 = pp[d + 3 * (D / 4)];
            float4 v  = vg[d];
            float mx = ((a0.x + a1.x) + (a2.x + a3.x)) * inv;
            float my = ((a0.y + a1.y) + (a2.y + a3.y)) * inv;
            float mz = ((a0.z + a1.z) + (a2.z + a3.z)) * inv;
            float mw = ((a0.w + a1.w) + (a2.w + a3.w)) * inv;
            dvm = fmaf(v.x, mx, fmaf(v.y, my, fmaf(v.z, mz, fmaf(v.w, mw, dvm))));
            dmm = fmaf(mx, mx, fmaf(my, my, fmaf(mz, mz, fmaf(mw, mw, dmm))));
            dvv = fmaf(v.x, v.x, fmaf(v.y, v.y, fmaf(v.z, v.z, fmaf(v.w, v.w, dvv))));
        }
        #pragma unroll
        for (int o = 16; o > 0; o >>= 1) {
            dvm += __shfl_down_sync(0xFFFFFFFFu, dvm, o);
            dmm += __shfl_down_sync(0xFFFFFFFFu, dmm, o);
            dvv += __shfl_down_sync(0xFFFFFFFFu, dvv, o);
        }
        if (lane == 0) { r0[w] = dvm; r1[w] = dmm; r2[w] = dvv; }
        __syncthreads();
        if (tid == 0) {
            float a  = r0[0] + r0[1] + r0[2] + r0[3];
            float m2 = r1[0] + r1[1] + r1[2] + r1[3];
            float v2 = r2[0] + r2[1] + r2[2] + r2[3];
            float denom = fmaxf(sqrtf(v2) * sqrtf(m2), 1e-8f);
            g_cos[bs] = a / denom;
        }
        __syncthreads();
    }

    __shared__ int last;
    if (tid == 0) {
        __threadfence();
        last = (atomicAdd(&g_ctr, 1) == NCOS - 1);
    }
    __syncthreads();

    if (last) {   // fused final reduction, fixed order -> deterministic
        float sum = 0.0f;
        #pragma unroll
        for (int i = tid; i < B * S; i += TPC) sum += __ldcg(&g_cos[i]);
        #pragma unroll
        for (int o = 16; o > 0; o >>= 1)
            sum += __shfl_down_sync(0xFFFFFFFFu, sum, o);
        __shared__ float sh[4];
        if (lane == 0) sh[w] = sum;
        __syncthreads();
        if (tid == 0) {
            out[0] = 1.0f - (sh[0] + sh[1] + sh[2] + sh[3]) / (float)(B * S);
            g_ctr = 0;   // reset for next graph replay
        }
    }
}

// ---------------------------------------------------------------------------
extern "C" void kernel_launch(void* const* d_in, const int* in_sizes, int n_in,
                              void* d_out, int out_size) {
    const int*   attr = (const int*)d_in[0];
    const float* text = (const float*)d_in[1];
    const float* vgs  = (const float*)d_in[2];
    float*       out  = (float*)d_out;

    const int smem = S * TPB * sizeof(float4);   // 128 KB dynamic
    static int attr_set = 0;
    if (!attr_set) {
        cudaFuncSetAttribute(k_accum, cudaFuncAttributeMaxDynamicSharedMemorySize, smem);
        attr_set = 1;
    }

    dim3 g1(B, LP);
    k_accum<<<g1, TPB, smem>>>(attr, text);
    k_cos<<<NCOS, TPC>>>(vgs, out);
}